// round 11
// baseline (speedup 1.0000x reference)
#include <cuda_runtime.h>
#include <cuda_bf16.h>
#include <cstdint>

#define B_ 128
#define T_ 2048
#define TT 64
#define NTILES 32
#define NTHR 512

// smem word offsets
#define WSH_OFF 0            // 32768: W bf16, 128 words/row, XOR swizzle
#define Q0_OFF  32768        // 8192: Q tile, packed 128 words/row, XOR swizzle
#define Q1_OFF  40960        // 8192   (Q0+Q1 also reused as z_part[64][256] at the end)
#define WG_OFF  49152        // 512: float2 {w[d], gpr[d]}
#define AP_OFF  49664        // 512: ap[8 part][64 tok]
#define RED_OFF 50176        // 8
#define PH_OFF  50184        // 512: ph[512] (prologue only)
#define SMEM_WORDS 50696

__device__ __forceinline__ float fast_tanh(float x) {
    float y;
    asm("tanh.approx.f32 %0, %1;" : "=f"(y) : "f"(x));
    return y;
}

__global__ __launch_bounds__(NTHR, 1)
void kFused(const float* __restrict__ input_q,
            const float* __restrict__ W_q,
            const float* __restrict__ wvec,
            const float* __restrict__ match_b,
            const int* __restrict__ mask_q,
            const float* __restrict__ input_p,
            const float* __restrict__ h_tm1,
            const float* __restrict__ W_p_r,
            const float* __restrict__ b_p_r,
            const float* __restrict__ b_q,
            float* __restrict__ out) {
    extern __shared__ uint32_t sh[];
    uint32_t* Wsh = sh + WSH_OFF;
    float2* wg_sh = reinterpret_cast<float2*>(sh + WG_OFF);
    float*  ap_sh = reinterpret_cast<float*>(sh + AP_OFF);   // [part 0..7][token 0..63]
    float*  red   = reinterpret_cast<float*>(sh + RED_OFF);
    float*  ph    = reinterpret_cast<float*>(sh + PH_OFF);

    int b    = blockIdx.x;
    int tid  = threadIdx.x;
    int lane = tid & 31, wid = tid >> 5;

    // ================= Prologue =================
    if (tid < 256) ph[tid] = input_p[b * 256 + tid];
    else           ph[tid] = h_tm1[b * 256 + (tid - 256)];
    __syncthreads();

    // gpr: 16 warps x 16 rows (warp-coalesced dot)
    for (int r = 0; r < 16; ++r) {
        int d = wid * 16 + r;
        const float4* row = reinterpret_cast<const float4*>(W_p_r + (size_t)d * 512);
        const float4* p4  = reinterpret_cast<const float4*>(ph);
        float acc = 0.f;
#pragma unroll
        for (int i = 0; i < 4; ++i) {
            float4 wv = row[i * 32 + lane];
            float4 pv = p4[i * 32 + lane];
            acc += wv.x * pv.x + wv.y * pv.y + wv.z * pv.z + wv.w * pv.w;
        }
#pragma unroll
        for (int o = 16; o; o >>= 1) acc += __shfl_xor_sync(0xffffffffu, acc, o);
        if (lane == 0) wg_sh[d] = make_float2(wvec[d], acc + b_p_r[d] + b_q[d]);
    }

    // W_q -> bf16 smem, XOR swizzle
    for (int i = tid; i < 256 * 128; i += NTHR) {
        int n = i >> 7, kw = i & 127;
        float2 f = reinterpret_cast<const float2*>(W_q)[n * 128 + kw];
        __nv_bfloat162 h = __floats2bfloat162_rn(f.x, f.y);
        int phys = (kw >> 2) ^ (n & 7);
        Wsh[n * 128 + phys * 4 + (kw & 3)] = *reinterpret_cast<uint32_t*>(&h);
    }

    const float   mb  = match_b[0];
    const float4* qb4 = reinterpret_cast<const float4*>(input_q + (size_t)b * T_ * 256);
    const int*    mqb = mask_q + (size_t)b * T_;

    // Q tile 0 -> Qsh0 (packed 128 words/row, XOR swizzle)
#pragma unroll
    for (int j = 0; j < 8; ++j) {
        int idx = tid + j * NTHR;
        float4 f = qb4[idx];
        int row = idx >> 6, c4 = idx & 63;
        __nv_bfloat162 h0 = __floats2bfloat162_rn(f.x, f.y);
        __nv_bfloat162 h1 = __floats2bfloat162_rn(f.z, f.w);
        uint32_t phys = (uint32_t)(c4 >> 1) ^ (uint32_t)(row & 7);
        *reinterpret_cast<uint2*>(&sh[Q0_OFF + row * 128 + phys * 4 + (c4 & 1) * 2]) =
            make_uint2(*reinterpret_cast<uint32_t*>(&h0), *reinterpret_cast<uint32_t*>(&h1));
    }
    __syncthreads();

    // ================= Main loop =================
    int warp_m = wid & 1;       // 2 warps over 64 tokens (m32)
    int warp_n = wid >> 1;      // 8 warps over 256 douts (n32)
    int t      = tid & 63;      // this thread's token slot (8 threads share a token)
    int dgrp   = tid >> 6;      // dout group: douts dgrp*32 .. +31

    float Sth = 0.f, Mth = -1e30f;    // only meaningful for tid<64
    float zacc[32];
#pragma unroll
    for (int j = 0; j < 32; ++j) zacc[j] = 0.f;

    for (int it = 0; it < NTILES; ++it) {
        const uint32_t Qcur_off = (it & 1) ? Q1_OFF : Q0_OFF;
        const uint32_t Qnxt_off = (it & 1) ? Q0_OFF : Q1_OFF;

        int mreg = mqb[it * TT + t];

        bool has_next = (it + 1 < NTILES);
        const float4* src = qb4 + (size_t)(it + 1) * TT * 64;

        // ---- kc loop: MMA + chunked staging (LDG at even kc, STS at odd kc)
        float c[8][4];
#pragma unroll
        for (int q = 0; q < 8; ++q) { c[q][0] = c[q][1] = c[q][2] = c[q][3] = 0.f; }

        float4 stg;
#pragma unroll
        for (int kc = 0; kc < 16; ++kc) {
            uint32_t a[2][4];
#pragma unroll
            for (int mt = 0; mt < 2; ++mt) {
                int arow  = warp_m * 32 + mt * 16 + (lane & 15);
                int physA = (kc * 2 + ((lane & 16) ? 1 : 0)) ^ (arow & 7);
                uint32_t aaddr = (uint32_t)__cvta_generic_to_shared(
                    &sh[Qcur_off + arow * 128 + physA * 4]);
                asm volatile("ldmatrix.sync.aligned.m8n8.x4.shared.b16 {%0,%1,%2,%3}, [%4];"
                             : "=r"(a[mt][0]), "=r"(a[mt][1]), "=r"(a[mt][2]), "=r"(a[mt][3])
                             : "r"(aaddr));
            }

            if (has_next) {
                if ((kc & 1) == 0) {
                    stg = src[tid + (kc >> 1) * NTHR];
                } else {
                    int idx = tid + (kc >> 1) * NTHR;
                    int row = idx >> 6, c4 = idx & 63;
                    __nv_bfloat162 h0 = __floats2bfloat162_rn(stg.x, stg.y);
                    __nv_bfloat162 h1 = __floats2bfloat162_rn(stg.z, stg.w);
                    uint32_t phys = (uint32_t)(c4 >> 1) ^ (uint32_t)(row & 7);
                    *reinterpret_cast<uint2*>(&sh[Qnxt_off + row * 128 + phys * 4 + (c4 & 1) * 2]) =
                        make_uint2(*reinterpret_cast<uint32_t*>(&h0),
                                   *reinterpret_cast<uint32_t*>(&h1));
                }
            }

#pragma unroll
            for (int np = 0; np < 2; ++np) {
                int row   = warp_n * 32 + np * 16 + (lane & 7) + ((lane & 16) ? 8 : 0);
                int physB = (kc * 2 + ((lane & 8) ? 1 : 0)) ^ (row & 7);
                uint32_t baddr = (uint32_t)__cvta_generic_to_shared(&Wsh[row * 128 + physB * 4]);
                uint32_t b0, b1, b2, b3;
                asm volatile("ldmatrix.sync.aligned.m8n8.x4.shared.b16 {%0,%1,%2,%3}, [%4];"
                             : "=r"(b0), "=r"(b1), "=r"(b2), "=r"(b3) : "r"(baddr));
#pragma unroll
                for (int mt = 0; mt < 2; ++mt) {
                    float* c0 = c[mt * 4 + np * 2];
                    float* c1 = c[mt * 4 + np * 2 + 1];
                    asm volatile(
                        "mma.sync.aligned.m16n8k16.row.col.f32.bf16.bf16.f32 "
                        "{%0,%1,%2,%3}, {%4,%5,%6,%7}, {%8,%9}, {%0,%1,%2,%3};"
                        : "+f"(c0[0]), "+f"(c0[1]), "+f"(c0[2]), "+f"(c0[3])
                        : "r"(a[mt][0]), "r"(a[mt][1]), "r"(a[mt][2]), "r"(a[mt][3]),
                          "r"(b0), "r"(b1));
                    asm volatile(
                        "mma.sync.aligned.m16n8k16.row.col.f32.bf16.bf16.f32 "
                        "{%0,%1,%2,%3}, {%4,%5,%6,%7}, {%8,%9}, {%0,%1,%2,%3};"
                        : "+f"(c1[0]), "+f"(c1[1]), "+f"(c1[2]), "+f"(c1[3])
                        : "r"(a[mt][0]), "r"(a[mt][1]), "r"(a[mt][2]), "r"(a[mt][3]),
                          "r"(b2), "r"(b3));
                }
            }
        }

        // ---- epilogue: tanh + dot(w), quad reduce, write ap[part][token]
#pragma unroll
        for (int mt = 0; mt < 2; ++mt) {
            float p0 = 0.f, p1 = 0.f;
#pragma unroll
            for (int np = 0; np < 2; ++np) {
#pragma unroll
                for (int j = 0; j < 2; ++j) {
                    int n = warp_n * 32 + np * 16 + j * 8 + (lane & 3) * 2;
                    float4 wg = *reinterpret_cast<const float4*>(&wg_sh[n]);
                    float* cc = c[mt * 4 + np * 2 + j];
                    p0 += wg.x * fast_tanh(cc[0] + wg.y) + wg.z * fast_tanh(cc[1] + wg.w);
                    p1 += wg.x * fast_tanh(cc[2] + wg.y) + wg.z * fast_tanh(cc[3] + wg.w);
                }
            }
            p0 += __shfl_xor_sync(0xffffffffu, p0, 1);
            p0 += __shfl_xor_sync(0xffffffffu, p0, 2);
            p1 += __shfl_xor_sync(0xffffffffu, p1, 1);
            p1 += __shfl_xor_sync(0xffffffffu, p1, 2);
            if ((lane & 3) == 0) {
                int row0 = warp_m * 32 + mt * 16 + (lane >> 2);
                ap_sh[warp_n * 64 + row0]     = p0;
                ap_sh[warp_n * 64 + row0 + 8] = p1;
            }
        }
        __syncthreads();   // BAR1: ap ready, STS(Qnxt) done

        // ---- all threads: redundant exp for token t, then z slice update
        {
            float raw = ((ap_sh[0 * 64 + t] + ap_sh[1 * 64 + t]) +
                         (ap_sh[2 * 64 + t] + ap_sh[3 * 64 + t])) +
                        ((ap_sh[4 * 64 + t] + ap_sh[5 * 64 + t]) +
                         (ap_sh[6 * 64 + t] + ap_sh[7 * 64 + t])) + mb;
            float mflt = (float)mreg;
            float x = fminf(fmaxf(raw, -15.f), 15.f) * mflt;
            float e = __expf(x - 15.f) * mflt;
            if (tid < 64) { Sth += e; Mth = fmaxf(Mth, x); }

#pragma unroll
            for (int i = 0; i < 4; ++i) {
                uint32_t cphys = ((uint32_t)(dgrp * 4 + i)) ^ (uint32_t)(t & 7);
                uint4 qw = *reinterpret_cast<const uint4*>(&sh[Qcur_off + t * 128 + cphys * 4]);
                uint32_t wv[4] = {qw.x, qw.y, qw.z, qw.w};
#pragma unroll
                for (int r = 0; r < 4; ++r) {
                    __nv_bfloat162 h2 = *reinterpret_cast<__nv_bfloat162*>(&wv[r]);
                    zacc[i * 8 + r * 2]     += e * __bfloat162float(__low2bfloat16(h2));
                    zacc[i * 8 + r * 2 + 1] += e * __bfloat162float(__high2bfloat16(h2));
                }
            }
        }
        __syncthreads();   // BAR2: Qcur reads done (next iter staging overwrites it)
    }

    // ================= Final =================
    // dump z partials: z_part[t][d] into Q0/Q1 area (64 x 256 floats = 64KB)
#pragma unroll
    for (int j = 0; j < 32; ++j) {
        sh[Q0_OFF + t * 256 + dgrp * 32 + j] = __float_as_uint(zacc[j]);
    }
    if (tid < 64) {
        float s = Sth, m = Mth;
#pragma unroll
        for (int o = 16; o; o >>= 1) {
            s += __shfl_xor_sync(0xffffffffu, s, o);
            m = fmaxf(m, __shfl_xor_sync(0xffffffffu, m, o));
        }
        if (lane == 0) { red[wid * 2] = s; red[wid * 2 + 1] = m; }
    }
    __syncthreads();

    if (tid < 256) {
        float Sp = red[0] + red[2];
        float Mg = fmaxf(red[1], red[3]);
        float denom = Sp + 1e-6f * __expf(Mg - 15.f);
        float zt = 0.f;
#pragma unroll 8
        for (int tt = 0; tt < 64; ++tt) {
            zt += __uint_as_float(sh[Q0_OFF + tt * 256 + tid]);
        }
        out[b * 512 + tid]       = input_p[b * 256 + tid];
        out[b * 512 + 256 + tid] = zt / denom;
    }
}

extern "C" void kernel_launch(void* const* d_in, const int* in_sizes, int n_in,
                              void* d_out, int out_size) {
    const float* input_p = (const float*)d_in[0];
    const float* input_q = (const float*)d_in[2];
    const int*   mask_q  = (const int*)d_in[3];
    const float* h_tm1   = (const float*)d_in[4];
    const float* W_p_r   = (const float*)d_in[5];
    const float* b_p_r   = (const float*)d_in[6];
    const float* W_q     = (const float*)d_in[7];
    const float* b_q     = (const float*)d_in[8];
    const float* wv      = (const float*)d_in[9];
    const float* match_b = (const float*)d_in[10];
    float* out = (float*)d_out;

    size_t smemF = (size_t)SMEM_WORDS * 4;
    cudaFuncSetAttribute(kFused, cudaFuncAttributeMaxDynamicSharedMemorySize, (int)smemF);
    kFused<<<B_, NTHR, smemF>>>(input_q, W_q, wv, match_b, mask_q,
                                input_p, h_tm1, W_p_r, b_p_r, b_q, out);
}

// round 12
// speedup vs baseline: 1.3291x; 1.3291x over previous
#include <cuda_runtime.h>
#include <cuda_bf16.h>
#include <cstdint>

#define B_ 128
#define T_ 2048
#define TT 64
#define NTILES 32
#define NTHR 1024

// smem word offsets
#define WSH_OFF 0            // 32768: W bf16, 128 words/row, XOR swizzle
#define Q0_OFF  32768        // 8192: Q tile, packed 128 words/row, XOR swizzle
#define Q1_OFF  40960        // 8192
#define WG_OFF  49152        // 512: float2 {w[d], gpr[d]}
#define E_OFF   49664        // 64
#define AP_OFF  49728        // 512: ap[64 tok][8 part]
#define RED_OFF 50240        // 8
#define ZB_OFF  50248        // 2048: zbuf[8][256] (ph[512] in prologue)
#define SMEM_WORDS 52296

__device__ __forceinline__ float fast_tanh(float x) {
    float y;
    asm("tanh.approx.f32 %0, %1;" : "=f"(y) : "f"(x));
    return y;
}

__global__ __launch_bounds__(NTHR, 1)
void kFused(const float* __restrict__ input_q,
            const float* __restrict__ W_q,
            const float* __restrict__ wvec,
            const float* __restrict__ match_b,
            const int* __restrict__ mask_q,
            const float* __restrict__ input_p,
            const float* __restrict__ h_tm1,
            const float* __restrict__ W_p_r,
            const float* __restrict__ b_p_r,
            const float* __restrict__ b_q,
            float* __restrict__ out) {
    extern __shared__ uint32_t sh[];
    uint32_t* Wsh = sh + WSH_OFF;
    float2* wg_sh = reinterpret_cast<float2*>(sh + WG_OFF);
    float*  e_sh  = reinterpret_cast<float*>(sh + E_OFF);
    float*  ap_sh = reinterpret_cast<float*>(sh + AP_OFF);   // [tok][part]
    float*  red   = reinterpret_cast<float*>(sh + RED_OFF);
    float*  zbuf  = reinterpret_cast<float*>(sh + ZB_OFF);

    int b    = blockIdx.x;
    int tid  = threadIdx.x;
    int lane = tid & 31, wid = tid >> 5;

    // ================= Prologue =================
    float* ph = zbuf;                       // [512] = [input_p | h_tm1]
    if (tid < 256)      ph[tid] = input_p[b * 256 + tid];
    else if (tid < 512) ph[tid] = h_tm1[b * 256 + (tid - 256)];
    __syncthreads();

    // gpr: 32 warps x 8 rows (warp-coalesced dot)
    for (int r = 0; r < 8; ++r) {
        int d = wid * 8 + r;
        const float4* row = reinterpret_cast<const float4*>(W_p_r + (size_t)d * 512);
        const float4* p4  = reinterpret_cast<const float4*>(ph);
        float acc = 0.f;
#pragma unroll
        for (int i = 0; i < 4; ++i) {
            float4 wv = row[i * 32 + lane];
            float4 pv = p4[i * 32 + lane];
            acc += wv.x * pv.x + wv.y * pv.y + wv.z * pv.z + wv.w * pv.w;
        }
#pragma unroll
        for (int o = 16; o; o >>= 1) acc += __shfl_xor_sync(0xffffffffu, acc, o);
        if (lane == 0) wg_sh[d] = make_float2(wvec[d], acc + b_p_r[d] + b_q[d]);
    }

    // W_q -> bf16 smem, XOR swizzle
    for (int i = tid; i < 256 * 128; i += NTHR) {
        int n = i >> 7, kw = i & 127;
        float2 f = reinterpret_cast<const float2*>(W_q)[n * 128 + kw];
        __nv_bfloat162 h = __floats2bfloat162_rn(f.x, f.y);
        int phys = (kw >> 2) ^ (n & 7);
        Wsh[n * 128 + phys * 4 + (kw & 3)] = *reinterpret_cast<uint32_t*>(&h);
    }

    const float   mb  = match_b[0];
    const float4* qb4 = reinterpret_cast<const float4*>(input_q + (size_t)b * T_ * 256);
    const int*    mqb = mask_q + (size_t)b * T_;

    // Q tile 0 -> Qsh0 (packed 128 words/row, XOR swizzle)
#pragma unroll
    for (int j = 0; j < 4; ++j) {
        int idx = tid + j * NTHR;
        float4 f = qb4[idx];
        int row = idx >> 6, c4 = idx & 63;
        __nv_bfloat162 h0 = __floats2bfloat162_rn(f.x, f.y);
        __nv_bfloat162 h1 = __floats2bfloat162_rn(f.z, f.w);
        uint32_t phys = (uint32_t)(c4 >> 1) ^ (uint32_t)(row & 7);
        *reinterpret_cast<uint2*>(&sh[Q0_OFF + row * 128 + phys * 4 + (c4 & 1) * 2]) =
            make_uint2(*reinterpret_cast<uint32_t*>(&h0), *reinterpret_cast<uint32_t*>(&h1));
    }
    __syncthreads();

    // ================= Main loop =================
    int warp_m = wid & 3;       // 4 warps over 64 tokens (m16 each)
    int warp_n = wid >> 2;      // 8 warps over 256 douts (n32 each)
    int zword = tid & 127;      // d-pair word
    int zoct  = tid >> 7;       // t-eighth (8 tokens)
    int zc    = zword >> 2, zr = zword & 3;

    float Sth = 0.f, Mth = -1e30f;      // tid<64
    float z0 = 0.f, z1 = 0.f;

    for (int it = 0; it < NTILES; ++it) {
        const uint32_t Qcur_off = (it & 1) ? Q1_OFF : Q0_OFF;
        const uint32_t Qnxt_off = (it & 1) ? Q0_OFF : Q1_OFF;

        int mreg = 0;
        if (tid < TT) mreg = mqb[it * TT + tid];

        bool has_next = (it + 1 < NTILES);
        const float4* src = qb4 + (size_t)(it + 1) * TT * 64;

        // ---- kc loop: MMA (m16n32 warp tile) + chunked staging
        float c[4][4];
#pragma unroll
        for (int q = 0; q < 4; ++q) { c[q][0] = c[q][1] = c[q][2] = c[q][3] = 0.f; }

        float4 stg;
#pragma unroll
        for (int kc = 0; kc < 16; ++kc) {
            // A fragment: m16 x k16 via one x4 ldmatrix
            uint32_t a0, a1, a2, a3;
            {
                int arow  = warp_m * 16 + (lane & 15);
                int physA = (kc * 2 + ((lane & 16) ? 1 : 0)) ^ (arow & 7);
                uint32_t aaddr = (uint32_t)__cvta_generic_to_shared(
                    &sh[Qcur_off + arow * 128 + physA * 4]);
                asm volatile("ldmatrix.sync.aligned.m8n8.x4.shared.b16 {%0,%1,%2,%3}, [%4];"
                             : "=r"(a0), "=r"(a1), "=r"(a2), "=r"(a3) : "r"(aaddr));
            }

            // staging: one float4 per thread per 4 kc steps
            if (has_next) {
                if ((kc & 3) == 0) {
                    stg = src[tid + (kc >> 2) * NTHR];
                } else if ((kc & 3) == 2) {
                    int idx = tid + (kc >> 2) * NTHR;
                    int row = idx >> 6, c4 = idx & 63;
                    __nv_bfloat162 h0 = __floats2bfloat162_rn(stg.x, stg.y);
                    __nv_bfloat162 h1 = __floats2bfloat162_rn(stg.z, stg.w);
                    uint32_t phys = (uint32_t)(c4 >> 1) ^ (uint32_t)(row & 7);
                    *reinterpret_cast<uint2*>(&sh[Qnxt_off + row * 128 + phys * 4 + (c4 & 1) * 2]) =
                        make_uint2(*reinterpret_cast<uint32_t*>(&h0),
                                   *reinterpret_cast<uint32_t*>(&h1));
                }
            }

#pragma unroll
            for (int np = 0; np < 2; ++np) {
                int row   = warp_n * 32 + np * 16 + (lane & 7) + ((lane & 16) ? 8 : 0);
                int physB = (kc * 2 + ((lane & 8) ? 1 : 0)) ^ (row & 7);
                uint32_t baddr = (uint32_t)__cvta_generic_to_shared(&Wsh[row * 128 + physB * 4]);
                uint32_t b0, b1, b2, b3;
                asm volatile("ldmatrix.sync.aligned.m8n8.x4.shared.b16 {%0,%1,%2,%3}, [%4];"
                             : "=r"(b0), "=r"(b1), "=r"(b2), "=r"(b3) : "r"(baddr));
                float* c0 = c[np * 2];
                float* c1 = c[np * 2 + 1];
                asm volatile(
                    "mma.sync.aligned.m16n8k16.row.col.f32.bf16.bf16.f32 "
                    "{%0,%1,%2,%3}, {%4,%5,%6,%7}, {%8,%9}, {%0,%1,%2,%3};"
                    : "+f"(c0[0]), "+f"(c0[1]), "+f"(c0[2]), "+f"(c0[3])
                    : "r"(a0), "r"(a1), "r"(a2), "r"(a3), "r"(b0), "r"(b1));
                asm volatile(
                    "mma.sync.aligned.m16n8k16.row.col.f32.bf16.bf16.f32 "
                    "{%0,%1,%2,%3}, {%4,%5,%6,%7}, {%8,%9}, {%0,%1,%2,%3};"
                    : "+f"(c1[0]), "+f"(c1[1]), "+f"(c1[2]), "+f"(c1[3])
                    : "r"(a0), "r"(a1), "r"(a2), "r"(a3), "r"(b2), "r"(b3));
            }
        }

        // ---- epilogue: tanh + dot(w), quad reduce, write ap[token][part]
        {
            float p0 = 0.f, p1 = 0.f;
#pragma unroll
            for (int nt = 0; nt < 4; ++nt) {
                int n = warp_n * 32 + nt * 8 + (lane & 3) * 2;
                float4 wg = *reinterpret_cast<const float4*>(&wg_sh[n]);   // {w0,g0,w1,g1}
                float* cc = c[nt];
                p0 += wg.x * fast_tanh(cc[0] + wg.y) + wg.z * fast_tanh(cc[1] + wg.w);
                p1 += wg.x * fast_tanh(cc[2] + wg.y) + wg.z * fast_tanh(cc[3] + wg.w);
            }
            p0 += __shfl_xor_sync(0xffffffffu, p0, 1);
            p0 += __shfl_xor_sync(0xffffffffu, p0, 2);
            p1 += __shfl_xor_sync(0xffffffffu, p1, 1);
            p1 += __shfl_xor_sync(0xffffffffu, p1, 2);
            if ((lane & 3) == 0) {
                int row0 = warp_m * 16 + (lane >> 2);
                ap_sh[row0 * 8 + warp_n]       = p0;
                ap_sh[(row0 + 8) * 8 + warp_n] = p1;
            }
        }
        __syncthreads();   // S1: ap ready, STS(Qnxt) done

        // ---- stage 1 (tid<64): e = exp(x-15)*m
        if (tid < TT) {
            const float* ap = &ap_sh[tid * 8];
            float raw = ((ap[0] + ap[1]) + (ap[2] + ap[3])) +
                        ((ap[4] + ap[5]) + (ap[6] + ap[7])) + mb;
            float mflt = (float)mreg;
            float x = fminf(fmaxf(raw, -15.f), 15.f) * mflt;
            float e = __expf(x - 15.f) * mflt;
            e_sh[tid] = e;
            Sth += e;
            Mth = fmaxf(Mth, x);
        }
        __syncthreads();   // S2: e_sh ready

        // ---- z update: thread owns d-pair zword, t-eighth zoct (8 tokens)
        {
            float a0 = 0.f, a1 = 0.f;
            int tb = zoct * 8;
#pragma unroll
            for (int k = 0; k < 8; ++k) {
                int t = tb + k;
                uint32_t qw = sh[Qcur_off + t * 128 + (((uint32_t)zc ^ (uint32_t)(t & 7)) << 2) + zr];
                __nv_bfloat162 h2 = *reinterpret_cast<__nv_bfloat162*>(&qw);
                float e = e_sh[t];
                a0 += e * __bfloat162float(__low2bfloat16(h2));
                a1 += e * __bfloat162float(__high2bfloat16(h2));
            }
            z0 += a0;
            z1 += a1;
        }
        __syncthreads();   // S3: Qcur reads done
    }

    // ================= Final =================
    if (tid < TT) {
        float s = Sth, m = Mth;
#pragma unroll
        for (int o = 16; o; o >>= 1) {
            s += __shfl_xor_sync(0xffffffffu, s, o);
            m = fmaxf(m, __shfl_xor_sync(0xffffffffu, m, o));
        }
        if (lane == 0) { red[wid * 2] = s; red[wid * 2 + 1] = m; }
    }
    __syncthreads();       // zbuf (aliases ph) safe
    zbuf[zoct * 256 + zword * 2]     = z0;
    zbuf[zoct * 256 + zword * 2 + 1] = z1;
    __syncthreads();

    if (tid < 256) {
        float Sp = red[0] + red[2];
        float Mg = fmaxf(red[1], red[3]);
        float denom = Sp + 1e-6f * __expf(Mg - 15.f);
        float zt = 0.f;
#pragma unroll
        for (int o = 0; o < 8; ++o) zt += zbuf[o * 256 + tid];
        out[b * 512 + tid]       = input_p[b * 256 + tid];
        out[b * 512 + 256 + tid] = zt / denom;
    }
}

extern "C" void kernel_launch(void* const* d_in, const int* in_sizes, int n_in,
                              void* d_out, int out_size) {
    const float* input_p = (const float*)d_in[0];
    const float* input_q = (const float*)d_in[2];
    const int*   mask_q  = (const int*)d_in[3];
    const float* h_tm1   = (const float*)d_in[4];
    const float* W_p_r   = (const float*)d_in[5];
    const float* b_p_r   = (const float*)d_in[6];
    const float* W_q     = (const float*)d_in[7];
    const float* b_q     = (const float*)d_in[8];
    const float* wv      = (const float*)d_in[9];
    const float* match_b = (const float*)d_in[10];
    float* out = (float*)d_out;

    size_t smemF = (size_t)SMEM_WORDS * 4;
    cudaFuncSetAttribute(kFused, cudaFuncAttributeMaxDynamicSharedMemorySize, (int)smemF);
    kFused<<<B_, NTHR, smemF>>>(input_q, W_q, wv, match_b, mask_q,
                                input_p, h_tm1, W_p_r, b_p_r, b_q, out);
}

// round 13
// speedup vs baseline: 1.3377x; 1.0064x over previous
#include <cuda_runtime.h>
#include <cuda_bf16.h>
#include <cstdint>

#define B_ 128
#define T_ 2048
#define TT 64
#define NTILES 32
#define NTHR 768

// smem word offsets
#define WSH_OFF 0            // 32768: W bf16, 128 words/row, XOR swizzle
#define Q0_OFF  32768        // 8192: Q tile, packed 128 words/row, XOR swizzle
#define Q1_OFF  40960        // 8192
#define WG_OFF  49152        // 512: float2 {w[d], gpr[d]}
#define E_OFF   49664        // 64
#define AP_OFF  49728        // 1024: ap[2][64 tok][8 part]
#define RED_OFF 50752        // 8
#define ZB_OFF  50760        // 512: zbuf[2][256] (ph[512] in prologue)
#define SMEM_WORDS 51272

__device__ __forceinline__ float fast_tanh(float x) {
    float y;
    asm("tanh.approx.f32 %0, %1;" : "=f"(y) : "f"(x));
    return y;
}

__global__ __launch_bounds__(NTHR, 1)
void kFused(const float* __restrict__ input_q,
            const float* __restrict__ W_q,
            const float* __restrict__ wvec,
            const float* __restrict__ match_b,
            const int* __restrict__ mask_q,
            const float* __restrict__ input_p,
            const float* __restrict__ h_tm1,
            const float* __restrict__ W_p_r,
            const float* __restrict__ b_p_r,
            const float* __restrict__ b_q,
            float* __restrict__ out) {
    extern __shared__ uint32_t sh[];
    uint32_t* Wsh = sh + WSH_OFF;
    float2* wg_sh = reinterpret_cast<float2*>(sh + WG_OFF);
    float*  e_sh  = reinterpret_cast<float*>(sh + E_OFF);
    float*  ap_sh = reinterpret_cast<float*>(sh + AP_OFF);   // [2][tok][part]
    float*  red   = reinterpret_cast<float*>(sh + RED_OFF);
    float*  zbuf  = reinterpret_cast<float*>(sh + ZB_OFF);

    int b    = blockIdx.x;
    int tid  = threadIdx.x;
    int lane = tid & 31, wid = tid >> 5;

    // ================= Prologue (all 768 threads) =================
    float* ph = zbuf;                       // [512] = [input_p | h_tm1]
    if (tid < 256)      ph[tid] = input_p[b * 256 + tid];
    else if (tid < 512) ph[tid] = h_tm1[b * 256 + (tid - 256)];
    __syncthreads();

    // gpr: warps 0..15 x 16 rows (warp-coalesced dot)
    if (wid < 16) {
        for (int r = 0; r < 16; ++r) {
            int d = wid * 16 + r;
            const float4* row = reinterpret_cast<const float4*>(W_p_r + (size_t)d * 512);
            const float4* p4  = reinterpret_cast<const float4*>(ph);
            float acc = 0.f;
#pragma unroll
            for (int i = 0; i < 4; ++i) {
                float4 wv = row[i * 32 + lane];
                float4 pv = p4[i * 32 + lane];
                acc += wv.x * pv.x + wv.y * pv.y + wv.z * pv.z + wv.w * pv.w;
            }
#pragma unroll
            for (int o = 16; o; o >>= 1) acc += __shfl_xor_sync(0xffffffffu, acc, o);
            if (lane == 0) wg_sh[d] = make_float2(wvec[d], acc + b_p_r[d] + b_q[d]);
        }
    }

    // W_q -> bf16 smem, XOR swizzle
    for (int i = tid; i < 256 * 128; i += NTHR) {
        int n = i >> 7, kw = i & 127;
        float2 f = reinterpret_cast<const float2*>(W_q)[n * 128 + kw];
        __nv_bfloat162 h = __floats2bfloat162_rn(f.x, f.y);
        int phys = (kw >> 2) ^ (n & 7);
        Wsh[n * 128 + phys * 4 + (kw & 3)] = *reinterpret_cast<uint32_t*>(&h);
    }

    const float   mb  = match_b[0];
    const float4* qb4 = reinterpret_cast<const float4*>(input_q + (size_t)b * T_ * 256);
    const int*    mqb = mask_q + (size_t)b * T_;

    // Q tile 0 -> Qsh0 (packed 128 words/row, XOR swizzle); 4096 float4, 768 thr
    for (int idx = tid; idx < 4096; idx += NTHR) {
        float4 f = qb4[idx];
        int row = idx >> 6, c4 = idx & 63;
        __nv_bfloat162 h0 = __floats2bfloat162_rn(f.x, f.y);
        __nv_bfloat162 h1 = __floats2bfloat162_rn(f.z, f.w);
        uint32_t phys = (uint32_t)(c4 >> 1) ^ (uint32_t)(row & 7);
        *reinterpret_cast<uint2*>(&sh[Q0_OFF + row * 128 + phys * 4 + (c4 & 1) * 2]) =
            make_uint2(*reinterpret_cast<uint32_t*>(&h0), *reinterpret_cast<uint32_t*>(&h1));
    }
    __syncthreads();

    // ================= Main loop =================
    // compute: tid<512 (16 warps, m32n32).  data: tid>=512 (8 warps).
    int warp_m = wid & 1;       // compute: 2 warps over 64 tokens
    int warp_n = wid >> 1;      // compute: 8 warps over 256 douts
    int dtid  = tid - 512;      // data thread id [0,256)
    int zword = dtid & 127;     // d-pair word
    int zhalf = dtid >> 7;      // t-half (32 tokens)
    int zc    = zword >> 2, zr = zword & 3;

    float Sth = 0.f, Mth = -1e30f;    // data dtid<64
    float z0 = 0.f, z1 = 0.f;         // data
    int   mprev = 0;                  // data dtid<64

    for (int it = 0; it <= NTILES; ++it) {
        if (tid < 512) {
            // ================= COMPUTE =================
            if (it < NTILES) {
                const uint32_t Qcur_off = (it & 1) ? Q1_OFF : Q0_OFF;
                float c[8][4];
#pragma unroll
                for (int q = 0; q < 8; ++q) { c[q][0] = c[q][1] = c[q][2] = c[q][3] = 0.f; }

#pragma unroll 4
                for (int kc = 0; kc < 16; ++kc) {
                    uint32_t a[2][4];
#pragma unroll
                    for (int mt = 0; mt < 2; ++mt) {
                        int arow  = warp_m * 32 + mt * 16 + (lane & 15);
                        int physA = (kc * 2 + ((lane & 16) ? 1 : 0)) ^ (arow & 7);
                        uint32_t aaddr = (uint32_t)__cvta_generic_to_shared(
                            &sh[Qcur_off + arow * 128 + physA * 4]);
                        asm volatile("ldmatrix.sync.aligned.m8n8.x4.shared.b16 {%0,%1,%2,%3}, [%4];"
                                     : "=r"(a[mt][0]), "=r"(a[mt][1]), "=r"(a[mt][2]), "=r"(a[mt][3])
                                     : "r"(aaddr));
                    }
#pragma unroll
                    for (int np = 0; np < 2; ++np) {
                        int row   = warp_n * 32 + np * 16 + (lane & 7) + ((lane & 16) ? 8 : 0);
                        int physB = (kc * 2 + ((lane & 8) ? 1 : 0)) ^ (row & 7);
                        uint32_t baddr = (uint32_t)__cvta_generic_to_shared(
                            &Wsh[row * 128 + physB * 4]);
                        uint32_t b0, b1, b2, b3;
                        asm volatile("ldmatrix.sync.aligned.m8n8.x4.shared.b16 {%0,%1,%2,%3}, [%4];"
                                     : "=r"(b0), "=r"(b1), "=r"(b2), "=r"(b3) : "r"(baddr));
#pragma unroll
                        for (int mt = 0; mt < 2; ++mt) {
                            float* c0 = c[mt * 4 + np * 2];
                            float* c1 = c[mt * 4 + np * 2 + 1];
                            asm volatile(
                                "mma.sync.aligned.m16n8k16.row.col.f32.bf16.bf16.f32 "
                                "{%0,%1,%2,%3}, {%4,%5,%6,%7}, {%8,%9}, {%0,%1,%2,%3};"
                                : "+f"(c0[0]), "+f"(c0[1]), "+f"(c0[2]), "+f"(c0[3])
                                : "r"(a[mt][0]), "r"(a[mt][1]), "r"(a[mt][2]), "r"(a[mt][3]),
                                  "r"(b0), "r"(b1));
                            asm volatile(
                                "mma.sync.aligned.m16n8k16.row.col.f32.bf16.bf16.f32 "
                                "{%0,%1,%2,%3}, {%4,%5,%6,%7}, {%8,%9}, {%0,%1,%2,%3};"
                                : "+f"(c1[0]), "+f"(c1[1]), "+f"(c1[2]), "+f"(c1[3])
                                : "r"(a[mt][0]), "r"(a[mt][1]), "r"(a[mt][2]), "r"(a[mt][3]),
                                  "r"(b2), "r"(b3));
                        }
                    }
                }

                // epilogue: tanh + dot(w), quad reduce -> ap[it&1]
                float* apb = ap_sh + (it & 1) * 512;
#pragma unroll
                for (int mt = 0; mt < 2; ++mt) {
                    float p0 = 0.f, p1 = 0.f;
#pragma unroll
                    for (int np = 0; np < 2; ++np) {
#pragma unroll
                        for (int j = 0; j < 2; ++j) {
                            int n = warp_n * 32 + np * 16 + j * 8 + (lane & 3) * 2;
                            float4 wg = *reinterpret_cast<const float4*>(&wg_sh[n]);
                            float* cc = c[mt * 4 + np * 2 + j];
                            p0 += wg.x * fast_tanh(cc[0] + wg.y) + wg.z * fast_tanh(cc[1] + wg.w);
                            p1 += wg.x * fast_tanh(cc[2] + wg.y) + wg.z * fast_tanh(cc[3] + wg.w);
                        }
                    }
                    p0 += __shfl_xor_sync(0xffffffffu, p0, 1);
                    p0 += __shfl_xor_sync(0xffffffffu, p0, 2);
                    p1 += __shfl_xor_sync(0xffffffffu, p1, 1);
                    p1 += __shfl_xor_sync(0xffffffffu, p1, 2);
                    if ((lane & 3) == 0) {
                        int row0 = warp_m * 32 + mt * 16 + (lane >> 2);
                        apb[row0 * 8 + warp_n]       = p0;
                        apb[(row0 + 8) * 8 + warp_n] = p1;
                    }
                }
            }
        } else {
            // ================= DATA (256 threads) =================
            bool ldg = (it + 1) < NTILES;
            const float4* src = qb4 + (size_t)(it + 1) * TT * 64;
            int mnext = 0;
            if (it < NTILES && dtid < 64) mnext = mqb[it * TT + dtid];

            // LDG chunk 1 early (latency hidden under stage1 + z)
            float4 pf[8];
            if (ldg) {
#pragma unroll
                for (int j = 0; j < 8; ++j) pf[j] = src[dtid + j * 256];
            }

            // stage 1 for tile it-1
            if (it > 0 && dtid < 64) {
                const float* ap = &ap_sh[((it - 1) & 1) * 512 + dtid * 8];
                float raw = ((ap[0] + ap[1]) + (ap[2] + ap[3])) +
                            ((ap[4] + ap[5]) + (ap[6] + ap[7])) + mb;
                float mflt = (float)mprev;
                float x = fminf(fmaxf(raw, -15.f), 15.f) * mflt;
                float e = __expf(x - 15.f) * mflt;
                e_sh[dtid] = e;
                Sth += e;
                Mth = fmaxf(Mth, x);
            }
            mprev = mnext;
            asm volatile("bar.sync 1, 256;" ::: "memory");

            // z for tile it-1 (reads Q[(it-1)&1])
            if (it > 0) {
                const uint32_t Qold_off = ((it - 1) & 1) ? Q1_OFF : Q0_OFF;
                float a0 = 0.f, a1 = 0.f;
                int tb = zhalf * 32;
#pragma unroll 8
                for (int k = 0; k < 32; ++k) {
                    int t = tb + k;
                    uint32_t qw = sh[Qold_off + t * 128 +
                                     (((uint32_t)zc ^ (uint32_t)(t & 7)) << 2) + zr];
                    __nv_bfloat162 h2 = *reinterpret_cast<__nv_bfloat162*>(&qw);
                    float e = e_sh[t];
                    a0 += e * __bfloat162float(__low2bfloat16(h2));
                    a1 += e * __bfloat162float(__high2bfloat16(h2));
                }
                z0 += a0;
                z1 += a1;
            }
            asm volatile("bar.sync 1, 256;" ::: "memory");   // z reads done -> buffer writable

            // STS chunk 1, then LDG+STS chunk 2, into Q[(it+1)&1]
            if (ldg) {
                const uint32_t Qn_off = ((it + 1) & 1) ? Q1_OFF : Q0_OFF;
#pragma unroll
                for (int j = 0; j < 8; ++j) {
                    int idx = dtid + j * 256;
                    int row = idx >> 6, c4 = idx & 63;
                    __nv_bfloat162 h0 = __floats2bfloat162_rn(pf[j].x, pf[j].y);
                    __nv_bfloat162 h1 = __floats2bfloat162_rn(pf[j].z, pf[j].w);
                    uint32_t phys = (uint32_t)(c4 >> 1) ^ (uint32_t)(row & 7);
                    *reinterpret_cast<uint2*>(&sh[Qn_off + row * 128 + phys * 4 + (c4 & 1) * 2]) =
                        make_uint2(*reinterpret_cast<uint32_t*>(&h0),
                                   *reinterpret_cast<uint32_t*>(&h1));
                }
#pragma unroll
                for (int j = 0; j < 8; ++j) pf[j] = src[dtid + (j + 8) * 256];
#pragma unroll
                for (int j = 0; j < 8; ++j) {
                    int idx = dtid + (j + 8) * 256;
                    int row = idx >> 6, c4 = idx & 63;
                    __nv_bfloat162 h0 = __floats2bfloat162_rn(pf[j].x, pf[j].y);
                    __nv_bfloat162 h1 = __floats2bfloat162_rn(pf[j].z, pf[j].w);
                    uint32_t phys = (uint32_t)(c4 >> 1) ^ (uint32_t)(row & 7);
                    *reinterpret_cast<uint2*>(&sh[Qn_off + row * 128 + phys * 4 + (c4 & 1) * 2]) =
                        make_uint2(*reinterpret_cast<uint32_t*>(&h0),
                                   *reinterpret_cast<uint32_t*>(&h1));
                }
            }
        }
        __syncthreads();
    }

    // ================= Final =================
    if (tid >= 512) {
        if (dtid < 64) {
            float s = Sth, m = Mth;
#pragma unroll
            for (int o = 16; o; o >>= 1) {
                s += __shfl_xor_sync(0xffffffffu, s, o);
                m = fmaxf(m, __shfl_xor_sync(0xffffffffu, m, o));
            }
            if (lane == 0) { red[(dtid >> 5) * 2] = s; red[(dtid >> 5) * 2 + 1] = m; }
        }
        zbuf[zhalf * 256 + zword * 2]     = z0;
        zbuf[zhalf * 256 + zword * 2 + 1] = z1;
    }
    __syncthreads();

    if (tid < 256) {
        float Sp = red[0] + red[2];
        float Mg = fmaxf(red[1], red[3]);
        float denom = Sp + 1e-6f * __expf(Mg - 15.f);
        float zt = zbuf[tid] + zbuf[256 + tid];
        out[b * 512 + tid]       = input_p[b * 256 + tid];
        out[b * 512 + 256 + tid] = zt / denom;
    }
}

extern "C" void kernel_launch(void* const* d_in, const int* in_sizes, int n_in,
                              void* d_out, int out_size) {
    const float* input_p = (const float*)d_in[0];
    const float* input_q = (const float*)d_in[2];
    const int*   mask_q  = (const int*)d_in[3];
    const float* h_tm1   = (const float*)d_in[4];
    const float* W_p_r   = (const float*)d_in[5];
    const float* b_p_r   = (const float*)d_in[6];
    const float* W_q     = (const float*)d_in[7];
    const float* b_q     = (const float*)d_in[8];
    const float* wv      = (const float*)d_in[9];
    const float* match_b = (const float*)d_in[10];
    float* out = (float*)d_out;

    size_t smemF = (size_t)SMEM_WORDS * 4;
    cudaFuncSetAttribute(kFused, cudaFuncAttributeMaxDynamicSharedMemorySize, (int)smemF);
    kFused<<<B_, NTHR, smemF>>>(input_q, W_q, wv, match_b, mask_q,
                                input_p, h_tm1, W_p_r, b_p_r, b_q, out);
}

// round 14
// speedup vs baseline: 1.4369x; 1.0742x over previous
#include <cuda_runtime.h>
#include <cuda_bf16.h>
#include <cstdint>

#define B_ 128
#define T_ 2048
#define TT 64
#define NTILES 32
#define QSTR 132
#define NTHR 512

// smem word offsets
#define WSH_OFF 0                          // 32768: W bf16, swizzled
#define Q0_OFF  32768                      // 8448
#define Q1_OFF  (Q0_OFF + TT * QSTR)       // 41216
#define WG_OFF  (Q1_OFF + TT * QSTR)       // 49664: float2 {w,gpr} x256
#define E_OFF   (WG_OFF + 512)             // 50176: e[64]
#define AP_OFF  (E_OFF + 64)               // 50240: ap[64][8]
#define RED_OFF (AP_OFF + 512)             // 50752: 8
#define ZB_OFF  (RED_OFF + 8)              // 50760: zbuf[4][256] (ph[512] in prologue)
#define SMEM_WORDS (ZB_OFF + 1024)

__device__ __forceinline__ float fast_tanh(float x) {
    float y;
    asm("tanh.approx.f32 %0, %1;" : "=f"(y) : "f"(x));
    return y;
}

__global__ __launch_bounds__(NTHR, 1)
void kFused(const float* __restrict__ input_q,
            const float* __restrict__ W_q,
            const float* __restrict__ wvec,
            const float* __restrict__ match_b,
            const int* __restrict__ mask_q,
            const float* __restrict__ input_p,
            const float* __restrict__ h_tm1,
            const float* __restrict__ W_p_r,
            const float* __restrict__ b_p_r,
            const float* __restrict__ b_q,
            float* __restrict__ out) {
    extern __shared__ uint32_t sh[];
    uint32_t* Wsh  = sh + WSH_OFF;
    uint32_t* Qsh0 = sh + Q0_OFF;
    uint32_t* Qsh1 = sh + Q1_OFF;
    float2* wg_sh = reinterpret_cast<float2*>(sh + WG_OFF);
    float*  e_sh  = reinterpret_cast<float*>(sh + E_OFF);
    float*  ap_sh = reinterpret_cast<float*>(sh + AP_OFF);
    float*  red   = reinterpret_cast<float*>(sh + RED_OFF);
    float*  zbuf  = reinterpret_cast<float*>(sh + ZB_OFF);

    int b    = blockIdx.x;
    int tid  = threadIdx.x;
    int lane = tid & 31, wid = tid >> 5;

    // ================= Prologue =================
    float* ph = zbuf;                       // [512] = [input_p | h_tm1]
    if (tid < 256) ph[tid] = input_p[b * 256 + tid];
    else           ph[tid] = h_tm1[b * 256 + (tid - 256)];
    __syncthreads();

    // gpr: 16 warps x 16 rows (warp-coalesced dot)
    for (int r = 0; r < 16; ++r) {
        int d = wid * 16 + r;
        const float4* row = reinterpret_cast<const float4*>(W_p_r + (size_t)d * 512);
        const float4* p4  = reinterpret_cast<const float4*>(ph);
        float acc = 0.f;
#pragma unroll
        for (int i = 0; i < 4; ++i) {
            float4 wv = row[i * 32 + lane];
            float4 pv = p4[i * 32 + lane];
            acc += wv.x * pv.x + wv.y * pv.y + wv.z * pv.z + wv.w * pv.w;
        }
#pragma unroll
        for (int o = 16; o; o >>= 1) acc += __shfl_xor_sync(0xffffffffu, acc, o);
        if (lane == 0) wg_sh[d] = make_float2(wvec[d], acc + b_p_r[d] + b_q[d]);
    }

    // W_q -> bf16 smem, 16B-chunk XOR swizzle
    for (int i = tid; i < 256 * 128; i += NTHR) {
        int n = i >> 7, kw = i & 127;
        float2 f = reinterpret_cast<const float2*>(W_q)[n * 128 + kw];
        __nv_bfloat162 h = __floats2bfloat162_rn(f.x, f.y);
        int phys = (kw >> 2) ^ (n & 7);
        Wsh[n * 128 + phys * 4 + (kw & 3)] = *reinterpret_cast<uint32_t*>(&h);
    }

    const float   mb  = match_b[0];
    const float4* qb4 = reinterpret_cast<const float4*>(input_q + (size_t)b * T_ * 256);
    const int*    mqb = mask_q + (size_t)b * T_;

    // ---- Preload tile 0 into Qsh0
#pragma unroll
    for (int j = 0; j < 8; ++j) {
        int idx = tid + j * NTHR;
        float4 f = qb4[idx];
        int row = idx >> 6, c4 = idx & 63;
        __nv_bfloat162 h0 = __floats2bfloat162_rn(f.x, f.y);
        __nv_bfloat162 h1 = __floats2bfloat162_rn(f.z, f.w);
        Qsh0[row * QSTR + c4 * 2]     = *reinterpret_cast<uint32_t*>(&h0);
        Qsh0[row * QSTR + c4 * 2 + 1] = *reinterpret_cast<uint32_t*>(&h1);
    }
    __syncthreads();

    // ================= Main loop (R5 structure, verbatim) =================
    int warp_m = wid & 1;        // 2 warps over 64 rows (32 each)
    int warp_n = wid >> 1;       // 8 warps over 256 cols (32 each)
    float Sth = 0.f, Mth = -1e30f;     // owned by threads tid<64
    float z0 = 0.f, z1 = 0.f;
    int zq = wid >> 2;                 // t-quarter (16 tokens each)
    int d0 = (tid & 127) * 2;          // this thread's output dims {d0, d0+1}
    int zword = tid & 127;

    for (int it = 0; it < NTILES; ++it) {
        uint32_t* Qcur = (it & 1) ? Qsh1 : Qsh0;
        uint32_t* Qnxt = (it & 1) ? Qsh0 : Qsh1;
        int t0 = it * TT;

        // ---- prefetch: mask for THIS tile + Q for next tile
        int mreg = mqb[t0 + (tid & 63)];
        bool has_next = (it + 1 < NTILES);
        float4 pf[8];
        if (has_next) {
            const float4* src = qb4 + (size_t)(t0 + TT) * 64;
#pragma unroll
            for (int j = 0; j < 8; ++j) pf[j] = src[tid + j * NTHR];
        }

        // ---- MMA: C[64 x 256] = Qtile @ W^T, warp tile m32 x n32
        float c[8][4];
#pragma unroll
        for (int q = 0; q < 8; ++q) { c[q][0] = c[q][1] = c[q][2] = c[q][3] = 0.f; }

#pragma unroll 4
        for (int kc = 0; kc < 16; ++kc) {
            uint32_t a[2][4];
#pragma unroll
            for (int mt = 0; mt < 2; ++mt) {
                int arow = warp_m * 32 + mt * 16 + (lane & 15);
                int acol = kc * 8 + ((lane & 16) ? 4 : 0);
                uint32_t aaddr = (uint32_t)__cvta_generic_to_shared(&Qcur[arow * QSTR + acol]);
                asm volatile("ldmatrix.sync.aligned.m8n8.x4.shared.b16 {%0,%1,%2,%3}, [%4];"
                             : "=r"(a[mt][0]), "=r"(a[mt][1]), "=r"(a[mt][2]), "=r"(a[mt][3])
                             : "r"(aaddr));
            }
#pragma unroll
            for (int np = 0; np < 2; ++np) {
                int row   = warp_n * 32 + np * 16 + (lane & 7) + ((lane & 16) ? 8 : 0);
                int chunk = kc * 2 + ((lane & 8) ? 1 : 0);
                int phys  = chunk ^ (row & 7);
                uint32_t baddr = (uint32_t)__cvta_generic_to_shared(&Wsh[row * 128 + phys * 4]);
                uint32_t b0, b1, b2, b3;
                asm volatile("ldmatrix.sync.aligned.m8n8.x4.shared.b16 {%0,%1,%2,%3}, [%4];"
                             : "=r"(b0), "=r"(b1), "=r"(b2), "=r"(b3) : "r"(baddr));
#pragma unroll
                for (int mt = 0; mt < 2; ++mt) {
                    float* c0 = c[mt * 4 + np * 2];
                    float* c1 = c[mt * 4 + np * 2 + 1];
                    asm volatile(
                        "mma.sync.aligned.m16n8k16.row.col.f32.bf16.bf16.f32 "
                        "{%0,%1,%2,%3}, {%4,%5,%6,%7}, {%8,%9}, {%0,%1,%2,%3};"
                        : "+f"(c0[0]), "+f"(c0[1]), "+f"(c0[2]), "+f"(c0[3])
                        : "r"(a[mt][0]), "r"(a[mt][1]), "r"(a[mt][2]), "r"(a[mt][3]),
                          "r"(b0), "r"(b1));
                    asm volatile(
                        "mma.sync.aligned.m16n8k16.row.col.f32.bf16.bf16.f32 "
                        "{%0,%1,%2,%3}, {%4,%5,%6,%7}, {%8,%9}, {%0,%1,%2,%3};"
                        : "+f"(c1[0]), "+f"(c1[1]), "+f"(c1[2]), "+f"(c1[3])
                        : "r"(a[mt][0]), "r"(a[mt][1]), "r"(a[mt][2]), "r"(a[mt][3]),
                          "r"(b2), "r"(b3));
                }
            }
        }

        // ---- store prefetched tile into other buffer (readers finished before
        //      previous iteration's S3)
        if (has_next) {
#pragma unroll
            for (int j = 0; j < 8; ++j) {
                int idx = tid + j * NTHR;
                int row = idx >> 6, c4 = idx & 63;
                __nv_bfloat162 h0 = __floats2bfloat162_rn(pf[j].x, pf[j].y);
                __nv_bfloat162 h1 = __floats2bfloat162_rn(pf[j].z, pf[j].w);
                Qnxt[row * QSTR + c4 * 2]     = *reinterpret_cast<uint32_t*>(&h0);
                Qnxt[row * QSTR + c4 * 2 + 1] = *reinterpret_cast<uint32_t*>(&h1);
            }
        }

        // ---- epilogue: tanh + dot(w), quad reduce, disjoint partial writes
#pragma unroll
        for (int mt = 0; mt < 2; ++mt) {
            float p0 = 0.f, p1 = 0.f;
#pragma unroll
            for (int np = 0; np < 2; ++np) {
#pragma unroll
                for (int j = 0; j < 2; ++j) {
                    int n = warp_n * 32 + np * 16 + j * 8 + (lane & 3) * 2;
                    float4 wg = *reinterpret_cast<const float4*>(&wg_sh[n]);   // {w0,g0,w1,g1}
                    float* cc = c[mt * 4 + np * 2 + j];
                    p0 += wg.x * fast_tanh(cc[0] + wg.y) + wg.z * fast_tanh(cc[1] + wg.w);
                    p1 += wg.x * fast_tanh(cc[2] + wg.y) + wg.z * fast_tanh(cc[3] + wg.w);
                }
            }
            p0 += __shfl_xor_sync(0xffffffffu, p0, 1);
            p0 += __shfl_xor_sync(0xffffffffu, p0, 2);
            p1 += __shfl_xor_sync(0xffffffffu, p1, 1);
            p1 += __shfl_xor_sync(0xffffffffu, p1, 2);
            if ((lane & 3) == 0) {
                int row0 = warp_m * 32 + mt * 16 + (lane >> 2);
                ap_sh[row0 * 8 + warp_n]       = p0;
                ap_sh[(row0 + 8) * 8 + warp_n] = p1;
            }
        }
        __syncthreads();   // S1: alpha partials ready

        // ---- stage 1 (tid<64): e = exp(x-15)*m ; accumulate S, M per-thread
        if (tid < TT) {
            const float* ap = &ap_sh[tid * 8];
            float raw = ((ap[0] + ap[1]) + (ap[2] + ap[3])) +
                        ((ap[4] + ap[5]) + (ap[6] + ap[7])) + mb;
            float mflt = (float)mreg;
            float x = fminf(fmaxf(raw, -15.f), 15.f) * mflt;
            float e = __expf(x - 15.f) * mflt;
            e_sh[tid] = e;
            Sth += e;
            Mth = fmaxf(Mth, x);
        }
        __syncthreads();   // S2: e_sh ready

        // ---- z update: thread owns dims {d0,d0+1}, t-quarter zq (16 tokens)
        {
            float a0 = 0.f, a1 = 0.f;
            int tbase = zq * 16;
#pragma unroll
            for (int ttk = 0; ttk < 16; ++ttk) {
                int t = tbase + ttk;
                uint32_t qw = Qcur[t * QSTR + zword];
                __nv_bfloat162 h2 = *reinterpret_cast<__nv_bfloat162*>(&qw);
                float e = e_sh[t];
                a0 += e * __bfloat162float(__low2bfloat16(h2));
                a1 += e * __bfloat162float(__high2bfloat16(h2));
            }
            z0 += a0;
            z1 += a1;
        }
        __syncthreads();   // S3: Qcur reads done; Qnxt visible
    }

    // ================= Final =================
    if (tid < TT) {
        float s = Sth, m = Mth;
#pragma unroll
        for (int o = 16; o; o >>= 1) {
            s += __shfl_xor_sync(0xffffffffu, s, o);
            m = fmaxf(m, __shfl_xor_sync(0xffffffffu, m, o));
        }
        if (lane == 0) { red[wid * 2] = s; red[wid * 2 + 1] = m; }
    }
    __syncthreads();       // zbuf (aliases nothing live now) safe
    zbuf[zq * 256 + d0]     = z0;
    zbuf[zq * 256 + d0 + 1] = z1;
    __syncthreads();

    if (tid < 256) {
        float Sp = red[0] + red[2];
        float Mg = fmaxf(red[1], red[3]);
        float denom = Sp + 1e-6f * __expf(Mg - 15.f);
        float zt = (zbuf[tid] + zbuf[256 + tid]) + (zbuf[512 + tid] + zbuf[768 + tid]);
        out[b * 512 + tid]       = input_p[b * 256 + tid];
        out[b * 512 + 256 + tid] = zt / denom;
    }
}

extern "C" void kernel_launch(void* const* d_in, const int* in_sizes, int n_in,
                              void* d_out, int out_size) {
    const float* input_p = (const float*)d_in[0];
    const float* input_q = (const float*)d_in[2];
    const int*   mask_q  = (const int*)d_in[3];
    const float* h_tm1   = (const float*)d_in[4];
    const float* W_p_r   = (const float*)d_in[5];
    const float* b_p_r   = (const float*)d_in[6];
    const float* W_q     = (const float*)d_in[7];
    const float* b_q     = (const float*)d_in[8];
    const float* wv      = (const float*)d_in[9];
    const float* match_b = (const float*)d_in[10];
    float* out = (float*)d_out;

    size_t smemF = (size_t)SMEM_WORDS * 4;
    cudaFuncSetAttribute(kFused, cudaFuncAttributeMaxDynamicSharedMemorySize, (int)smemF);
    kFused<<<B_, NTHR, smemF>>>(input_q, W_q, wv, match_b, mask_q,
                                input_p, h_tm1, W_p_r, b_p_r, b_q, out);
}